// round 7
// baseline (speedup 1.0000x reference)
#include <cuda_runtime.h>
#include <math.h>

// Problem constants: B=64, S=2048, I=256, H=256, G=2H=512
#define BATCH 64
#define SEQ   2048
#define HID   256
#define GATES 512
#define WROWS 272          // 256 real rows + 16 zero pad rows
#define ZROW  256          // index of a guaranteed all-zero row

// -------- scratch (static device arrays; no allocation) --------
__device__ float g_gx[67108864];          // (B*S, 512) fp32 = 256 MB
__device__ float g_WhT0[WROWS * GATES];   // [j][g], rows >=256 are zero
__device__ float g_WiT1[WROWS * GATES];
__device__ float g_WhT1[WROWS * GATES];

// ---------------------------------------------------------------
// Kernel 0: transpose weights into padded [j][g] layout; zero pad rows.
// ---------------------------------------------------------------
__global__ void prep_kernel(const float* __restrict__ Wh0,
                            const float* __restrict__ Wi1,
                            const float* __restrict__ Wh1)
{
    int idx = blockIdx.x * 256 + threadIdx.x;
    const int perp = WROWS * GATES;       // 139264
    if (idx < 3 * perp) {
        int m = idx / perp;
        int e = idx - m * perp;
        int j = e >> 9;                   // row
        int g = e & 511;                  // col
        const float* src = (m == 0) ? Wh0 : (m == 1) ? Wi1 : Wh1;
        float*       dst = (m == 0) ? g_WhT0 : (m == 1) ? g_WiT1 : g_WhT1;
        dst[e] = (j < HID) ? src[g * HID + j] : 0.0f;
    }
}

// ---------------------------------------------------------------
// Kernel 1: gx0 = (x @ Wi0^T + bi0) + bh0   (unchanged — passed)
// ---------------------------------------------------------------
__global__ void __launch_bounds__(256, 2)
gemm_gx_kernel(const float* __restrict__ x,
               const float* __restrict__ Wi0,
               const float* __restrict__ bi0,
               const float* __restrict__ bh0)
{
    __shared__ float As[32][68];
    __shared__ float Bs[32][68];

    const int m0  = blockIdx.x * 64;
    const int n0  = blockIdx.y * 64;
    const int tid = threadIdx.x;
    const int tx  = tid & 15;
    const int ty  = tid >> 4;

    float acc[4][4];
#pragma unroll
    for (int i = 0; i < 4; i++)
#pragma unroll
        for (int j = 0; j < 4; j++) acc[i][j] = 0.f;

    for (int k0 = 0; k0 < 256; k0 += 32) {
#pragma unroll
        for (int v = 0; v < 2; v++) {
            int idx = tid + v * 256;
            int r   = idx >> 3;
            int kk  = (idx & 7) << 2;
            float4 av = *reinterpret_cast<const float4*>(
                x + (size_t)(m0 + r) * 256 + (k0 + kk));
            As[kk + 0][r] = av.x; As[kk + 1][r] = av.y;
            As[kk + 2][r] = av.z; As[kk + 3][r] = av.w;
            float4 bv = *reinterpret_cast<const float4*>(
                Wi0 + (size_t)(n0 + r) * 256 + (k0 + kk));
            Bs[kk + 0][r] = bv.x; Bs[kk + 1][r] = bv.y;
            Bs[kk + 2][r] = bv.z; Bs[kk + 3][r] = bv.w;
        }
        __syncthreads();
#pragma unroll
        for (int k = 0; k < 32; k++) {
            float4 av = *reinterpret_cast<const float4*>(&As[k][ty << 2]);
            float4 bv = *reinterpret_cast<const float4*>(&Bs[k][tx << 2]);
            float aa[4] = {av.x, av.y, av.z, av.w};
            float bb[4] = {bv.x, bv.y, bv.z, bv.w};
#pragma unroll
            for (int i = 0; i < 4; i++)
#pragma unroll
                for (int j = 0; j < 4; j++)
                    acc[i][j] = __fmaf_rn(aa[i], bb[j], acc[i][j]);
        }
        __syncthreads();
    }

    float4 b1 = *reinterpret_cast<const float4*>(bi0 + n0 + (tx << 2));
    float4 b2 = *reinterpret_cast<const float4*>(bh0 + n0 + (tx << 2));

#pragma unroll
    for (int i = 0; i < 4; i++) {
        int r = m0 + (ty << 2) + i;
        float4 o;
        o.x = __fadd_rn(__fadd_rn(acc[i][0], b1.x), b2.x);
        o.y = __fadd_rn(__fadd_rn(acc[i][1], b1.y), b2.y);
        o.z = __fadd_rn(__fadd_rn(acc[i][2], b1.z), b2.z);
        o.w = __fadd_rn(__fadd_rn(acc[i][3], b1.w), b2.w);
        *reinterpret_cast<float4*>(g_gx + (size_t)r * GATES + n0 + (tx << 2)) = o;
    }
}

// ---------------------------------------------------------------
// float2 active-row sum: two independent single-accumulator chains in
// strictly ascending j order (bit-identical to dense ascending FMA dot
// with binary h; ZROW pads add exact +0.0f). 16 independent LDG.64 per
// chunk -> MLP=16 per thread, no predication.
// ---------------------------------------------------------------
__device__ __forceinline__ float2 matvec2(const float* __restrict__ Wb,
                                          const int* __restrict__ lst, int n16)
{
    float2 m = make_float2(0.f, 0.f);
    const int4* l4 = reinterpret_cast<const int4*>(lst);
    const int nb = n16 >> 4;
    for (int k = 0; k < nb; k++) {
        int4 a = l4[k * 4 + 0];
        int4 b = l4[k * 4 + 1];
        int4 c = l4[k * 4 + 2];
        int4 d = l4[k * 4 + 3];
        float2 w0  = *reinterpret_cast<const float2*>(Wb + ((size_t)a.x << 9));
        float2 w1  = *reinterpret_cast<const float2*>(Wb + ((size_t)a.y << 9));
        float2 w2  = *reinterpret_cast<const float2*>(Wb + ((size_t)a.z << 9));
        float2 w3  = *reinterpret_cast<const float2*>(Wb + ((size_t)a.w << 9));
        float2 w4  = *reinterpret_cast<const float2*>(Wb + ((size_t)b.x << 9));
        float2 w5  = *reinterpret_cast<const float2*>(Wb + ((size_t)b.y << 9));
        float2 w6  = *reinterpret_cast<const float2*>(Wb + ((size_t)b.z << 9));
        float2 w7  = *reinterpret_cast<const float2*>(Wb + ((size_t)b.w << 9));
        float2 w8  = *reinterpret_cast<const float2*>(Wb + ((size_t)c.x << 9));
        float2 w9  = *reinterpret_cast<const float2*>(Wb + ((size_t)c.y << 9));
        float2 w10 = *reinterpret_cast<const float2*>(Wb + ((size_t)c.z << 9));
        float2 w11 = *reinterpret_cast<const float2*>(Wb + ((size_t)c.w << 9));
        float2 w12 = *reinterpret_cast<const float2*>(Wb + ((size_t)d.x << 9));
        float2 w13 = *reinterpret_cast<const float2*>(Wb + ((size_t)d.y << 9));
        float2 w14 = *reinterpret_cast<const float2*>(Wb + ((size_t)d.z << 9));
        float2 w15 = *reinterpret_cast<const float2*>(Wb + ((size_t)d.w << 9));
        m.x = __fadd_rn(m.x, w0.x);  m.y = __fadd_rn(m.y, w0.y);
        m.x = __fadd_rn(m.x, w1.x);  m.y = __fadd_rn(m.y, w1.y);
        m.x = __fadd_rn(m.x, w2.x);  m.y = __fadd_rn(m.y, w2.y);
        m.x = __fadd_rn(m.x, w3.x);  m.y = __fadd_rn(m.y, w3.y);
        m.x = __fadd_rn(m.x, w4.x);  m.y = __fadd_rn(m.y, w4.y);
        m.x = __fadd_rn(m.x, w5.x);  m.y = __fadd_rn(m.y, w5.y);
        m.x = __fadd_rn(m.x, w6.x);  m.y = __fadd_rn(m.y, w6.y);
        m.x = __fadd_rn(m.x, w7.x);  m.y = __fadd_rn(m.y, w7.y);
        m.x = __fadd_rn(m.x, w8.x);  m.y = __fadd_rn(m.y, w8.y);
        m.x = __fadd_rn(m.x, w9.x);  m.y = __fadd_rn(m.y, w9.y);
        m.x = __fadd_rn(m.x, w10.x); m.y = __fadd_rn(m.y, w10.y);
        m.x = __fadd_rn(m.x, w11.x); m.y = __fadd_rn(m.y, w11.y);
        m.x = __fadd_rn(m.x, w12.x); m.y = __fadd_rn(m.y, w12.y);
        m.x = __fadd_rn(m.x, w13.x); m.y = __fadd_rn(m.y, w13.y);
        m.x = __fadd_rn(m.x, w14.x); m.y = __fadd_rn(m.y, w14.y);
        m.x = __fadd_rn(m.x, w15.x); m.y = __fadd_rn(m.y, w15.y);
    }
    return m;
}

// XLA logistic: 1/(1+exp(-x)), exp via fp64 rounded to f32 (unchanged — passed).
__device__ __forceinline__ float sigmoid_ref(float g)
{
    float ef = (float)exp(-(double)g);
    return __fdiv_rn(1.0f, __fadd_rn(1.0f, ef));
}

// ---------------------------------------------------------------
// Kernel 2: fused 2-layer spiking-LSTM scan. One CTA per batch element.
// 512 threads, float2 gate-pairs.
//   phase 1: warps 0-7  -> Wh0 . h0(t-1)   (gates + gx -> gsm)
//            warps 8-15 -> Wh1 . h1(t-1)   (-> mh_sm)   [runs concurrently]
//   L0 update -> lst0
//   phase 2: warps 0-7  -> Wi1 . h0(t)     (combine with mh_sm)
//   L1 update -> lst1, output
// ---------------------------------------------------------------
__global__ void __launch_bounds__(512, 1)
recurrent_kernel(const float* __restrict__ bi1,
                 const float* __restrict__ bh1,
                 float* __restrict__ out)
{
    const int b    = blockIdx.x;
    const int tid  = threadIdx.x;
    const int lane = tid & 31;
    const int warp = tid >> 5;
    const int pr   = tid & 255;          // gate-pair index within half

    __shared__ float c0s[HID], c1s[HID];
    __shared__ float gsm[GATES];
    __shared__ float mh_sm[GATES];
    __shared__ alignas(16) int lst0[WROWS];
    __shared__ alignas(16) int lst1[WROWS];
    __shared__ int wb[8];

    if (tid < HID) { c0s[tid] = 0.f; c1s[tid] = 0.f; }

    float2 bi1v = make_float2(0.f, 0.f), bh1v = make_float2(0.f, 0.f);
    if (tid < 256) {
        bi1v = reinterpret_cast<const float2*>(bi1)[tid];
        bh1v = reinterpret_cast<const float2*>(bh1)[tid];
    }
    int n0p = 0, n1p = 0;                // padded active counts (registers)
    __syncthreads();

    const float* gxb  = g_gx + (size_t)b * ((size_t)SEQ * GATES);
    float*       outb = out  + (size_t)b * ((size_t)SEQ * HID);

    for (int t = 0; t < SEQ; ++t) {
        // ---------------- phase 1: two recurrent matvecs in parallel --------
        if (tid < 256) {
            float2 gx2 = __ldcg(reinterpret_cast<const float2*>(
                                    gxb + (size_t)t * GATES) + tid);
            float2 m0  = matvec2(g_WhT0 + 2 * tid, lst0, n0p);
            float2 g2;
            g2.x = __fadd_rn(gx2.x, m0.x);        // g_t + h @ Wh0^T
            g2.y = __fadd_rn(gx2.y, m0.y);
            *reinterpret_cast<float2*>(&gsm[2 * tid]) = g2;
        } else {
            float2 mh = matvec2(g_WhT1 + 2 * pr, lst1, n1p);
            *reinterpret_cast<float2*>(&mh_sm[2 * pr]) = mh;
        }
        __syncthreads();                           // (A)

        // ---------------- L0 update ----------------
        bool p = false; unsigned bal = 0;
        if (tid < HID) {
            float f  = sigmoid_ref(gsm[tid]);
            float ct = gsm[tid + HID];
            float c  = __fadd_rn(__fmul_rn(f, c0s[tid]),
                                 __fmul_rn(__fsub_rn(1.0f, f), ct));
            c0s[tid] = c;
            p = (c > 0.f);
            bal = __ballot_sync(0xffffffffu, p);
            if (lane == 0) wb[warp] = __popc(bal);
        }
        __syncthreads();                           // (B)
        {
            int tot = 0, off = 0;
#pragma unroll
            for (int i = 0; i < 8; i++) {
                int c = wb[i];
                if (i < warp) off += c;
                tot += c;
            }
            n0p = (tot + 15) & ~15;
            if (p) lst0[off + __popc(bal & ((1u << lane) - 1u))] = tid;
            if (tid < 16 && tot + tid < n0p) lst0[tot + tid] = ZROW;
        }
        __syncthreads();                           // (C)

        // ---------------- phase 2: Wi1 . h0_new ----------------
        float2 gi = make_float2(0.f, 0.f);
        if (tid < 256) {
            float2 mi = matvec2(g_WiT1 + 2 * tid, lst0, n0p);
            gi.x = __fadd_rn(__fadd_rn(mi.x, bi1v.x), bh1v.x);
            gi.y = __fadd_rn(__fadd_rn(mi.y, bi1v.y), bh1v.y);
            // combine with Wh1 matvec (mh_sm stable since sync A)
            float2 mh = *reinterpret_cast<const float2*>(&mh_sm[2 * tid]);
            float2 g2;
            g2.x = __fadd_rn(gi.x, mh.x);          // ((Wi1.h0+bi1)+bh1)+Wh1.h1
            g2.y = __fadd_rn(gi.y, mh.y);
            *reinterpret_cast<float2*>(&gsm[2 * tid]) = g2;
        }
        __syncthreads();                           // (D)

        // ---------------- L1 update ----------------
        p = false; bal = 0;
        if (tid < HID) {
            float f  = sigmoid_ref(gsm[tid]);
            float ct = gsm[tid + HID];
            float c  = __fadd_rn(__fmul_rn(f, c1s[tid]),
                                 __fmul_rn(__fsub_rn(1.0f, f), ct));
            c1s[tid] = c;
            float h  = (c > 0.f) ? 1.f : 0.f;
            p = (c > 0.f);
            outb[(size_t)t * HID + tid] = h;
            bal = __ballot_sync(0xffffffffu, p);
            if (lane == 0) wb[warp] = __popc(bal);
        }
        __syncthreads();                           // (E)
        {
            int tot = 0, off = 0;
#pragma unroll
            for (int i = 0; i < 8; i++) {
                int c = wb[i];
                if (i < warp) off += c;
                tot += c;
            }
            n1p = (tot + 15) & ~15;
            if (p) lst1[off + __popc(bal & ((1u << lane) - 1u))] = tid;
            if (tid < 16 && tot + tid < n1p) lst1[tot + tid] = ZROW;
        }
        __syncthreads();                           // (F)
    }

    // finals: h_n (2,B,H) then c_n (2,B,H) after the (B,S,H) output
    if (tid < HID) {
        const size_t HN = (size_t)BATCH * SEQ * HID;
        const size_t CN = HN + (size_t)2 * BATCH * HID;
        out[HN + ((size_t)0 * BATCH + b) * HID + tid] = (c0s[tid] > 0.f) ? 1.f : 0.f;
        out[HN + ((size_t)1 * BATCH + b) * HID + tid] = (c1s[tid] > 0.f) ? 1.f : 0.f;
        out[CN + ((size_t)0 * BATCH + b) * HID + tid] = c0s[tid];
        out[CN + ((size_t)1 * BATCH + b) * HID + tid] = c1s[tid];
    }
}

// ---------------------------------------------------------------
extern "C" void kernel_launch(void* const* d_in, const int* in_sizes, int n_in,
                              void* d_out, int out_size)
{
    const float* x   = (const float*)d_in[0];
    const float* Wi0 = (const float*)d_in[1];
    const float* bi0 = (const float*)d_in[2];
    const float* Wh0 = (const float*)d_in[3];
    const float* bh0 = (const float*)d_in[4];
    const float* Wi1 = (const float*)d_in[5];
    const float* bi1 = (const float*)d_in[6];
    const float* Wh1 = (const float*)d_in[7];
    const float* bh1 = (const float*)d_in[8];
    float* out = (float*)d_out;

    prep_kernel<<<1632, 256>>>(Wh0, Wi1, Wh1);

    dim3 gg(2048, 8);
    gemm_gx_kernel<<<gg, 256>>>(x, Wi0, bi0, bh0);

    recurrent_kernel<<<BATCH, 512>>>(bi1, bh1, out);
}